// round 1
// baseline (speedup 1.0000x reference)
#include <cuda_runtime.h>
#include <cuda_bf16.h>
#include <cstddef>

// Problem constants
#define S 2048
#define E 1024
#define H 16
#define HD 64
#define P 64
#define SCALE 0.125f   // 1/sqrt(64)

// Scratch (allocation-free rule: __device__ globals)
__device__ float g_q[S * E];
__device__ float g_k[S * E];
__device__ float g_v[S * E];
__device__ float g_rel[S * S];
__device__ float g_attn[S * E];

// ---------------------------------------------------------------------------
// GEMM: C[M,N] = A[M,K] * B[N,K]^T (+ bias[N])
// BM=BN=128, BK=8, 256 threads, 8x8 per thread (split 4+4 fragments)
// ---------------------------------------------------------------------------
__global__ __launch_bounds__(256) void gemm128_abt(
    const float* __restrict__ A, const float* __restrict__ B,
    const float* __restrict__ bias, float* __restrict__ C,
    int M, int N, int K, int lda, int ldb, int ldc)
{
    __shared__ float As[8][132];
    __shared__ float Bs[8][132];
    const int tid = threadIdx.x;
    const int tx = tid & 15, ty = tid >> 4;
    const int row0 = blockIdx.y * 128;
    const int col0 = blockIdx.x * 128;

    float acc[8][8];
#pragma unroll
    for (int i = 0; i < 8; i++)
#pragma unroll
        for (int j = 0; j < 8; j++) acc[i][j] = 0.f;

    for (int k0 = 0; k0 < K; k0 += 8) {
#pragma unroll
        for (int i = 0; i < 4; i++) {
            int idx = tid + i * 256;
            int r = idx >> 3, c = idx & 7;
            As[c][r] = A[(size_t)(row0 + r) * lda + k0 + c];
            Bs[c][r] = B[(size_t)(col0 + r) * ldb + k0 + c];
        }
        __syncthreads();
#pragma unroll
        for (int kk = 0; kk < 8; kk++) {
            float a[8], b[8];
            *(float4*)&a[0] = *(const float4*)&As[kk][ty * 4];
            *(float4*)&a[4] = *(const float4*)&As[kk][64 + ty * 4];
            *(float4*)&b[0] = *(const float4*)&Bs[kk][tx * 4];
            *(float4*)&b[4] = *(const float4*)&Bs[kk][64 + tx * 4];
#pragma unroll
            for (int i = 0; i < 8; i++)
#pragma unroll
                for (int j = 0; j < 8; j++) acc[i][j] += a[i] * b[j];
        }
        __syncthreads();
    }

#pragma unroll
    for (int i = 0; i < 8; i++) {
        int r = row0 + ((i < 4) ? (ty * 4 + i) : (64 + ty * 4 + i - 4));
#pragma unroll
        for (int j = 0; j < 8; j++) {
            int c = col0 + ((j < 4) ? (tx * 4 + j) : (64 + tx * 4 + j - 4));
            float v = acc[i][j];
            if (bias) v += bias[c];
            C[(size_t)r * ldc + c] = v;
        }
    }
}

// ---------------------------------------------------------------------------
// Scores: w[h,s,t] = (q_h[s,:]·k_h[t,:] + rel[s,t]) * SCALE   (raw, pre-softmax)
// Same tiling as gemm128_abt, K=64, grid (16,16,H)
// ---------------------------------------------------------------------------
__global__ __launch_bounds__(256) void score128(
    const float* __restrict__ rel, float* __restrict__ w)
{
    const int h = blockIdx.z;
    const float* A = g_q + h * HD;   // lda = E
    const float* B = g_k + h * HD;   // ldb = E
    float* C = w + (size_t)h * S * S;

    __shared__ float As[8][132];
    __shared__ float Bs[8][132];
    const int tid = threadIdx.x;
    const int tx = tid & 15, ty = tid >> 4;
    const int row0 = blockIdx.y * 128;
    const int col0 = blockIdx.x * 128;

    float acc[8][8];
#pragma unroll
    for (int i = 0; i < 8; i++)
#pragma unroll
        for (int j = 0; j < 8; j++) acc[i][j] = 0.f;

    for (int k0 = 0; k0 < HD; k0 += 8) {
#pragma unroll
        for (int i = 0; i < 4; i++) {
            int idx = tid + i * 256;
            int r = idx >> 3, c = idx & 7;
            As[c][r] = A[(size_t)(row0 + r) * E + k0 + c];
            Bs[c][r] = B[(size_t)(col0 + r) * E + k0 + c];
        }
        __syncthreads();
#pragma unroll
        for (int kk = 0; kk < 8; kk++) {
            float a[8], b[8];
            *(float4*)&a[0] = *(const float4*)&As[kk][ty * 4];
            *(float4*)&a[4] = *(const float4*)&As[kk][64 + ty * 4];
            *(float4*)&b[0] = *(const float4*)&Bs[kk][tx * 4];
            *(float4*)&b[4] = *(const float4*)&Bs[kk][64 + tx * 4];
#pragma unroll
            for (int i = 0; i < 8; i++)
#pragma unroll
                for (int j = 0; j < 8; j++) acc[i][j] += a[i] * b[j];
        }
        __syncthreads();
    }

#pragma unroll
    for (int i = 0; i < 8; i++) {
        int r = row0 + ((i < 4) ? (ty * 4 + i) : (64 + ty * 4 + i - 4));
#pragma unroll
        for (int j = 0; j < 8; j++) {
            int c = col0 + ((j < 4) ? (tx * 4 + j) : (64 + tx * 4 + j - 4));
            C[(size_t)r * S + c] = (acc[i][j] + rel[(size_t)r * S + c]) * SCALE;
        }
    }
}

// ---------------------------------------------------------------------------
// Row softmax in-place over w: one block per (h,s) row of 2048
// ---------------------------------------------------------------------------
__global__ __launch_bounds__(256) void softmax_rows(float* __restrict__ w)
{
    float* p = w + (size_t)blockIdx.x * S;
    const int tid = threadIdx.x;
    __shared__ float red[256];

    float vals[8];
    float mx = -1e30f;
#pragma unroll
    for (int i = 0; i < 8; i++) {
        vals[i] = p[tid + i * 256];
        mx = fmaxf(mx, vals[i]);
    }
    red[tid] = mx;
    __syncthreads();
    for (int s2 = 128; s2 > 0; s2 >>= 1) {
        if (tid < s2) red[tid] = fmaxf(red[tid], red[tid + s2]);
        __syncthreads();
    }
    mx = red[0];
    __syncthreads();

    float sum = 0.f;
#pragma unroll
    for (int i = 0; i < 8; i++) {
        vals[i] = __expf(vals[i] - mx);
        sum += vals[i];
    }
    red[tid] = sum;
    __syncthreads();
    for (int s2 = 128; s2 > 0; s2 >>= 1) {
        if (tid < s2) red[tid] += red[tid + s2];
        __syncthreads();
    }
    float inv = 1.f / red[0];
#pragma unroll
    for (int i = 0; i < 8; i++) p[tid + i * 256] = vals[i] * inv;
}

// ---------------------------------------------------------------------------
// attn[s, h*64+d] = sum_t w[h,s,t] * v[t, h*64+d]
// C = A(w_h)[S,S] * B(v_h)[S,64].  BM=128, BN=64, BK=16. grid (1,16,H)
// ---------------------------------------------------------------------------
__global__ __launch_bounds__(256) void attn_gemm(const float* __restrict__ w)
{
    const int h = blockIdx.z;
    const float* A = w + (size_t)h * S * S;   // lda = S
    const float* B = g_v + h * HD;            // B[t][d] = v[t*E + h*HD + d]
    float* C = g_attn + h * HD;               // ldc = E

    __shared__ float As[16][132];  // transposed [k][m]
    __shared__ float Bs[16][64];   // [k][n]
    const int tid = threadIdx.x;
    const int tx = tid & 15, ty = tid >> 4;
    const int row0 = blockIdx.y * 128;

    float acc[8][4];
#pragma unroll
    for (int i = 0; i < 8; i++)
#pragma unroll
        for (int j = 0; j < 4; j++) acc[i][j] = 0.f;

    for (int k0 = 0; k0 < S; k0 += 16) {
#pragma unroll
        for (int i = 0; i < 8; i++) {
            int idx = tid + i * 256;
            int r = idx >> 4, c = idx & 15;
            As[c][r] = A[(size_t)(row0 + r) * S + k0 + c];
        }
#pragma unroll
        for (int i = 0; i < 4; i++) {
            int idx = tid + i * 256;
            int r = idx >> 6, c = idx & 63;
            Bs[r][c] = B[(size_t)(k0 + r) * E + c];
        }
        __syncthreads();
#pragma unroll
        for (int kk = 0; kk < 16; kk++) {
            float a[8], b[4];
            *(float4*)&a[0] = *(const float4*)&As[kk][ty * 4];
            *(float4*)&a[4] = *(const float4*)&As[kk][64 + ty * 4];
            *(float4*)&b[0] = *(const float4*)&Bs[kk][tx * 4];
#pragma unroll
            for (int i = 0; i < 8; i++)
#pragma unroll
                for (int j = 0; j < 4; j++) acc[i][j] += a[i] * b[j];
        }
        __syncthreads();
    }

#pragma unroll
    for (int i = 0; i < 8; i++) {
        int r = row0 + ((i < 4) ? (ty * 4 + i) : (64 + ty * 4 + i - 4));
#pragma unroll
        for (int j = 0; j < 4; j++) {
            int c = tx * 4 + j;
            C[(size_t)r * E + c] = acc[i][j];
        }
    }
}

// ---------------------------------------------------------------------------
// Launch
// ---------------------------------------------------------------------------
extern "C" void kernel_launch(void* const* d_in, const int* in_sizes, int n_in,
                              void* d_out, int out_size)
{
    (void)in_sizes; (void)n_in; (void)out_size;
    const float* query = (const float*)d_in[0];
    const float* key   = (const float*)d_in[1];
    const float* value = (const float*)d_in[2];
    const float* sim   = (const float*)d_in[3];
    const float* Wq    = (const float*)d_in[4];
    const float* bq    = (const float*)d_in[5];
    const float* Wk    = (const float*)d_in[6];
    const float* bk    = (const float*)d_in[7];
    const float* Wv    = (const float*)d_in[8];
    const float* bv    = (const float*)d_in[9];
    const float* Wo    = (const float*)d_in[10];
    const float* bo    = (const float*)d_in[11];

    float* out = (float*)d_out;                 // [S,E]
    float* w   = out + (size_t)S * E;           // [H,S,S]

    float *gq, *gk, *gv, *grel, *gattn;
    cudaGetSymbolAddress((void**)&gq,    g_q);
    cudaGetSymbolAddress((void**)&gk,    g_k);
    cudaGetSymbolAddress((void**)&gv,    g_v);
    cudaGetSymbolAddress((void**)&grel,  g_rel);
    cudaGetSymbolAddress((void**)&gattn, g_attn);

    dim3 blk(256);

    // Projections: q/k/v = X @ W^T + b
    gemm128_abt<<<dim3(E / 128, S / 128), blk>>>(query, Wq, bq, gq, S, E, E, E, E, E);
    gemm128_abt<<<dim3(E / 128, S / 128), blk>>>(key,   Wk, bk, gk, S, E, E, E, E, E);
    gemm128_abt<<<dim3(E / 128, S / 128), blk>>>(value, Wv, bv, gv, S, E, E, E, E, E);

    // rel = sim @ sim^T
    gemm128_abt<<<dim3(S / 128, S / 128), blk>>>(sim, sim, nullptr, grel, S, S, P, P, P, S);

    // scores (raw) -> w
    score128<<<dim3(S / 128, S / 128, H), blk>>>(grel, w);

    // softmax in place over last dim
    softmax_rows<<<H * S, blk>>>(w);

    // attn = w @ v_h  (per head) -> g_attn [S,E]
    attn_gemm<<<dim3(1, S / 128, H), blk>>>(w);

    // out = attn @ Wo^T + bo
    gemm128_abt<<<dim3(E / 128, S / 128), blk>>>(gattn, Wo, bo, out, S, E, E, E, E, E);
}